// round 1
// baseline (speedup 1.0000x reference)
#include <cuda_runtime.h>
#include <cstdint>

// Problem constants (fixed by the dataset: B=1, P=8192, N=16384, C=64)
#define GRID_DIM 10
#define NCELLS   (GRID_DIM * GRID_DIM * GRID_DIM)
#define NPTS_MAX 16384
#define CFEAT    64
#define OUTC     115          // 64 fcd + 3 xyz + 24 sin + 24 cos
#define KNN      10
#define R2F      0.01f
#define RADIUSF  0.1f
#define CANDMAX  192          // per-query candidate cap (E[#in-ball] ~ 68)
#define WPB      8            // warps (queries) per block

// ---- scratch: static __device__ arrays (no allocation allowed) ----
__device__ int    g_cell_count[NCELLS];
__device__ int    g_cell_start[NCELLS + 1];
__device__ int    g_cell_cursor[NCELLS];
__device__ float4 g_sorted[NPTS_MAX];   // {x, y, z, __int_as_float(orig_idx)}

__device__ __forceinline__ int cell_coord(float v) {
    int c = (int)(v * 10.0f);
    return c < 0 ? 0 : (c > 9 ? 9 : c);
}
__device__ __forceinline__ int cell_of(float x, float y, float z) {
    return (cell_coord(z) * GRID_DIM + cell_coord(y)) * GRID_DIM + cell_coord(x);
}

// ---- grid build ----
__global__ void zero_kernel() {
    int i = blockIdx.x * blockDim.x + threadIdx.x;
    if (i < NCELLS) g_cell_count[i] = 0;
}

__global__ void count_kernel(const float* __restrict__ pcd, int N) {
    int i = blockIdx.x * blockDim.x + threadIdx.x;
    if (i < N) {
        int c = cell_of(pcd[3 * i], pcd[3 * i + 1], pcd[3 * i + 2]);
        atomicAdd(&g_cell_count[c], 1);
    }
}

__global__ void scan_kernel() {   // 1 block, 1024 threads: scan 1000 cells
    __shared__ int s[1024];
    int i = threadIdx.x;
    int val = (i < NCELLS) ? g_cell_count[i] : 0;
    s[i] = val;
    __syncthreads();
    #pragma unroll
    for (int off = 1; off < 1024; off <<= 1) {
        int t = (i >= off) ? s[i - off] : 0;
        __syncthreads();
        s[i] += t;
        __syncthreads();
    }
    if (i < NCELLS) {
        int excl = s[i] - val;
        g_cell_start[i] = excl;
        g_cell_cursor[i] = excl;
    }
    if (i == NCELLS - 1) g_cell_start[NCELLS] = s[i];
}

__global__ void scatter_kernel(const float* __restrict__ pcd, int N) {
    int i = blockIdx.x * blockDim.x + threadIdx.x;
    if (i < N) {
        float x = pcd[3 * i], y = pcd[3 * i + 1], z = pcd[3 * i + 2];
        int c = cell_of(x, y, z);
        int pos = atomicAdd(&g_cell_cursor[c], 1);
        g_sorted[pos] = make_float4(x, y, z, __int_as_float(i));
    }
}

// ---- main: warp-per-query radius KNN + aggregate + positional encoding ----
__global__ void __launch_bounds__(WPB * 32)
knn_kernel(const float* __restrict__ xyz,
           const float* __restrict__ feat,
           float* __restrict__ out, int P) {
    __shared__ unsigned long long buf[WPB][CANDMAX];
    __shared__ int cnt[WPB];

    const int w    = threadIdx.x >> 5;
    const int lane = threadIdx.x & 31;
    const int q    = blockIdx.x * WPB + w;
    if (q >= P) return;                       // warp-uniform

    const float qx = xyz[3 * q], qy = xyz[3 * q + 1], qz = xyz[3 * q + 2];
    // replicate reference: |q|^2 via non-FMA sequential reduce
    const float qq = __fadd_rn(__fadd_rn(__fmul_rn(qx, qx), __fmul_rn(qy, qy)),
                               __fmul_rn(qz, qz));

    if (lane == 0) cnt[w] = 0;
    __syncwarp();

    const int ix = cell_coord(qx), iy = cell_coord(qy), iz = cell_coord(qz);
    const int x0 = max(ix - 1, 0), x1 = min(ix + 1, GRID_DIM - 1);
    const int y0 = max(iy - 1, 0), y1 = min(iy + 1, GRID_DIM - 1);
    const int z0 = max(iz - 1, 0), z1 = min(iz + 1, GRID_DIM - 1);

    for (int zz = z0; zz <= z1; zz++) {
        for (int yy = y0; yy <= y1; yy++) {
            const int cbase = (zz * GRID_DIM + yy) * GRID_DIM;
            const int segS = g_cell_start[cbase + x0];
            const int segE = g_cell_start[cbase + x1 + 1];
            for (int j0 = segS; j0 < segE; j0 += 32) {
                const int j = j0 + lane;
                bool pred = false;
                unsigned long long key = 0ULL;
                if (j < segE) {
                    float4 p = g_sorted[j];
                    // |p|^2 non-FMA sequential
                    float pp = __fadd_rn(__fadd_rn(__fmul_rn(p.x, p.x),
                                                   __fmul_rn(p.y, p.y)),
                                         __fmul_rn(p.z, p.z));
                    // dot via FMA accumulation chain (Eigen k-loop order)
                    float dot = fmaf(qz, p.z, fmaf(qy, p.y, __fmul_rn(qx, p.x)));
                    float d2 = __fsub_rn(__fadd_rn(qq, pp), __fmul_rn(2.0f, dot));
                    if (d2 < R2F) {
                        pred = true;
                        int b = __float_as_int(d2);
                        unsigned ub = (unsigned)b;
                        unsigned u = ub ^ ((b >= 0) ? 0x80000000u : 0xFFFFFFFFu);
                        key = ((unsigned long long)u << 32) |
                              (unsigned)__float_as_int(p.w);
                    }
                }
                unsigned bal = __ballot_sync(0xffffffffu, pred);
                if (bal) {
                    int base = cnt[w];
                    if (pred) {
                        int pos = base + __popc(bal & ((1u << lane) - 1u));
                        if (pos < CANDMAX) buf[w][pos] = key;
                    }
                    if (lane == 0) cnt[w] = base + __popc(bal);
                }
                __syncwarp();
            }
        }
    }
    __syncwarp();

    const int m = min(cnt[w], CANDMAX);

    // pull my buffer slots into registers
    const int SLOTS = (CANDMAX + 31) / 32;    // 6
    unsigned long long v[SLOTS];
    #pragma unroll
    for (int t = 0; t < SLOTS; t++) {
        int s = lane + 32 * t;
        v[t] = (s < m) ? buf[w][s] : ~0ULL;
    }

    // select K smallest keys via repeated warp-min; lane i keeps neighbor i
    unsigned long long mykey = ~0ULL;
    #pragma unroll
    for (int i = 0; i < KNN; i++) {
        unsigned long long mn = v[0];
        #pragma unroll
        for (int t = 1; t < SLOTS; t++) mn = (v[t] < mn) ? v[t] : mn;
        #pragma unroll
        for (int off = 16; off; off >>= 1) {
            unsigned long long o = __shfl_xor_sync(0xffffffffu, mn, off);
            mn = (o < mn) ? o : mn;
        }
        if (lane == i) mykey = mn;
        #pragma unroll
        for (int t = 0; t < SLOTS; t++) if (v[t] == mn) v[t] = ~0ULL;
    }

    // weights (lanes >= KNN or empty slots contribute 0)
    float wr = 0.0f;
    int nidx = 0;
    if (mykey != ~0ULL) {
        unsigned u = (unsigned)(mykey >> 32);
        unsigned ub = u ^ (((int)u < 0) ? 0x80000000u : 0xFFFFFFFFu);
        float d2 = __int_as_float((int)ub);
        nidx = (int)(mykey & 0xffffffffULL);
        float d2c = fmaxf(d2, 0.0f);
        float dist = sqrtf(d2c + 1e-12f);
        if (dist < RADIUSF) wr = 1.0f / (dist + 1e-8f);
    }
    float ws = wr;
    #pragma unroll
    for (int off = 16; off; off >>= 1) ws += __shfl_xor_sync(0xffffffffu, ws, off);
    float wn = wr / (ws + 1e-8f);

    // weighted feature gather: each lane owns channels (2*lane, 2*lane+1)
    float acc0 = 0.0f, acc1 = 0.0f;
    #pragma unroll
    for (int i = 0; i < KNN; i++) {
        float wi = __shfl_sync(0xffffffffu, wn, i);
        int ii = __shfl_sync(0xffffffffu, nidx, i);
        if (wi != 0.0f) {
            const float2 f2 =
                *reinterpret_cast<const float2*>(feat + (size_t)ii * CFEAT + 2 * lane);
            acc0 = fmaf(wi, f2.x, acc0);
            acc1 = fmaf(wi, f2.y, acc1);
        }
    }
    float* oq = out + (size_t)q * OUTC;
    oq[2 * lane]     = acc0;
    oq[2 * lane + 1] = acc1;

    // positional encoding: channels 64..114 = [xyz(3), sin(24), cos(24)]
    for (int j = lane; j < 51; j += 32) {
        float vv;
        if (j < 3) {
            vv = (j == 0) ? qx : ((j == 1) ? qy : qz);
        } else {
            int s = (j < 27) ? (j - 3) : (j - 27);
            int d = s % 3;
            float coord = (d == 0) ? qx : ((d == 1) ? qy : qz);
            float a = coord * (float)(1 << (s / 3));
            vv = (j < 27) ? sinf(a) : cosf(a);
        }
        oq[64 + j] = vv;
    }
}

extern "C" void kernel_launch(void* const* d_in, const int* in_sizes, int n_in,
                              void* d_out, int out_size) {
    const float* xyz  = (const float*)d_in[0];   // [1, P, 3]
    const float* pcd  = (const float*)d_in[1];   // [1, N, 3]
    const float* feat = (const float*)d_in[2];   // [1, N, 64]
    float* out = (float*)d_out;                  // [1, P, 115]
    const int P = in_sizes[0] / 3;
    const int N = in_sizes[1] / 3;

    zero_kernel<<<(NCELLS + 255) / 256, 256>>>();
    count_kernel<<<(N + 255) / 256, 256>>>(pcd, N);
    scan_kernel<<<1, 1024>>>();
    scatter_kernel<<<(N + 255) / 256, 256>>>(pcd, N);
    knn_kernel<<<(P + WPB - 1) / WPB, WPB * 32>>>(xyz, feat, out, P);
}